// round 1
// baseline (speedup 1.0000x reference)
#include <cuda_runtime.h>
#include <cuda_bf16.h>
#include <math.h>

// ---------------------------------------------------------------------------
// Problem constants (match reference)
// ---------------------------------------------------------------------------
#define S_LEN   4096
#define BATCH   4
#define HCH     256
#define ICH     512
#define NDEPTH  8
#define KWIDTH  7
#define NOUT    256
// log(S/2/pi) = 11*ln2 - ln(pi)
#define LOGC    6.4798891f

// ---------------------------------------------------------------------------
// Scratch (device globals; no cudaMalloc allowed)
// ---------------------------------------------------------------------------
__device__ float g_A  [BATCH*HCH*S_LEN];   // carry a
__device__ float g_Bc [BATCH*HCH*S_LEN];   // carry b
__device__ float g_O  [BATCH*HCH*S_LEN];   // out = b + pos_embd; later gate tmp
__device__ float g_T1 [BATCH*ICH*S_LEN];   // ff intermediate / concat buffer
__device__ float g_T2 [BATCH*ICH*S_LEN];   // ff intermediate
__device__ float g_D  [BATCH*HCH*S_LEN];   // branch d / logits
__device__ float g_P  [BATCH*HCH*S_LEN];   // branch p
__device__ float g_S  [BATCH*HCH*S_LEN];   // branch s
__device__ float g_NLL[BATCH*S_LEN];       // per-token nll

// ---------------------------------------------------------------------------
// Embedding gather: a[b,h,s] = emb[inp[b,s], h]; bcarry[b,h,s] = emb[tok, 256+h]
// ---------------------------------------------------------------------------
__global__ void embed_kernel(const float* __restrict__ emb,
                             const int*   __restrict__ inp,
                             float* __restrict__ A, float* __restrict__ Bc)
{
    int tid = blockIdx.x * blockDim.x + threadIdx.x;     // B*S threads
    int b = tid >> 12;
    int s = tid & (S_LEN - 1);
    int tok = inp[tid];
    const float* e = emb + (size_t)tok * (2 * HCH);
    size_t base = ((size_t)b * HCH) * S_LEN + s;
#pragma unroll 4
    for (int h = 0; h < HCH; h++) {
        A [base + (size_t)h * S_LEN] = e[h];
        Bc[base + (size_t)h * S_LEN] = e[HCH + h];
    }
}

// ---------------------------------------------------------------------------
// out = b + pos_embd;  pe[h,s] = sin((s+1)*fe[h]) / DEPTH
// ---------------------------------------------------------------------------
__global__ void addpos_kernel(const float* __restrict__ Bc, float* __restrict__ O)
{
    int idx = blockIdx.x * blockDim.x + threadIdx.x;     // B*H*S
    int s = idx & (S_LEN - 1);
    int h = (idx >> 12) & (HCH - 1);
    float feat = (float)(h + 1);
    float additive = (float)((h + 1) & 1);
    float fe0 = (feat - additive) * 0.5f * (8.0f / (float)HCH) - LOGC;
    float fe  = expf(fe0) + additive * 3.14159265358979f;
    float pe  = sinf((float)(s + 1) * fe) * 0.125f;      // STD/DEPTH = 1/8
    O[idx] = Bc[idx] + pe;
}

// ---------------------------------------------------------------------------
// Tiled causal-conv / GEMM.
//   Y[b,o,s] = sum_ci sum_k W[o,ci,k] * X[b,ci,s-(KW-1)+k]   (zero left pad)
// grid: (S/TS, Cout/64, B), 256 threads, thread tile 4(out) x MS(seq)
// ---------------------------------------------------------------------------
template<int KW, int TS, int MS>
__global__ void __launch_bounds__(256)
conv_gemm(const float* __restrict__ X, const float* __restrict__ W,
          float* __restrict__ Y, int Cin, int Cout)
{
    constexpr int TO   = 64;
    constexpr int TK   = 16;
    constexpr int HALO = KW - 1;
    constexpr int XW   = TS + HALO;
    constexpr int XSTR = (XW + 3) & ~3;

    __shared__ float Xs[TK][XSTR];
    __shared__ float Ws[TK][TO][KW];

    const int s0 = blockIdx.x * TS;
    const int o0 = blockIdx.y * TO;
    const int bb = blockIdx.z;
    const float* Xb = X + (size_t)bb * Cin * S_LEN;
    float*       Yb = Y + (size_t)bb * Cout * S_LEN;

    const int tid = threadIdx.x;
    const int tx  = tid & 15;
    const int ty  = tid >> 4;

    float acc[4][MS];
#pragma unroll
    for (int i = 0; i < 4; i++)
#pragma unroll
        for (int j = 0; j < MS; j++) acc[i][j] = 0.f;

    for (int c0 = 0; c0 < Cin; c0 += TK) {
        // load X tile with left halo (zero pad at sequence start)
        for (int idx = tid; idx < TK * XW; idx += 256) {
            int ci = idx / XW;
            int t  = idx - ci * XW;
            int sg = s0 - HALO + t;
            Xs[ci][t] = (sg >= 0) ? Xb[(size_t)(c0 + ci) * S_LEN + sg] : 0.f;
        }
        // load W tile: per out-row, TK*KW contiguous floats
        const float* Wb = W + (size_t)o0 * Cin * KW + (size_t)c0 * KW;
        for (int idx = tid; idx < TO * TK * KW; idx += 256) {
            int o = idx / (TK * KW);
            int r = idx - o * (TK * KW);
            int ci = r / KW;
            int k  = r - ci * KW;
            Ws[ci][o][k] = Wb[(size_t)o * Cin * KW + r];
        }
        __syncthreads();

#pragma unroll
        for (int ci = 0; ci < TK; ci++) {
            float xv[MS + HALO];
#pragma unroll
            for (int t = 0; t < MS + HALO; t++) xv[t] = Xs[ci][tx * MS + t];
            float wv[4][KW];
#pragma unroll
            for (int oo = 0; oo < 4; oo++)
#pragma unroll
                for (int k = 0; k < KW; k++) wv[oo][k] = Ws[ci][ty * 4 + oo][k];
#pragma unroll
            for (int oo = 0; oo < 4; oo++)
#pragma unroll
                for (int j = 0; j < MS; j++) {
                    float a = acc[oo][j];
#pragma unroll
                    for (int k = 0; k < KW; k++) a = fmaf(wv[oo][k], xv[j + k], a);
                    acc[oo][j] = a;
                }
        }
        __syncthreads();
    }

#pragma unroll
    for (int oo = 0; oo < 4; oo++) {
        float* yr = Yb + (size_t)(o0 + ty * 4 + oo) * S_LEN + s0 + tx * MS;
#pragma unroll
        for (int j = 0; j < MS; j++) yr[j] = acc[oo][j];
    }
}

// ---------------------------------------------------------------------------
// Block reduction helper (256 threads = 8 warps)
// ---------------------------------------------------------------------------
__device__ __forceinline__ float block_reduce(float v, float* sm)
{
    int lane = threadIdx.x & 31;
    int w    = threadIdx.x >> 5;
#pragma unroll
    for (int o = 16; o > 0; o >>= 1) v += __shfl_xor_sync(0xffffffffu, v, o);
    if (lane == 0) sm[w] = v;
    __syncthreads();
    if (w == 0) {
        float r = (lane < 8) ? sm[lane] : 0.f;
#pragma unroll
        for (int o = 4; o > 0; o >>= 1) r += __shfl_xor_sync(0xffffffffu, r, o);
        if (lane == 0) sm[32] = r;
    }
    __syncthreads();
    float out = sm[32];
    __syncthreads();
    return out;
}

// ---------------------------------------------------------------------------
// act_norm over the sequence axis (row length S). One block per (b,c) row.
//   o = relu(x); o -= mean(o); y = o * 64/(||o||+1e-5)  [+ Res]
// In-place safe (row fully in registers before writeback).
// ---------------------------------------------------------------------------
__global__ void actnorm_kernel(const float* __restrict__ X,
                               const float* __restrict__ Res,
                               float* __restrict__ Y)
{
    __shared__ float sm[33];
    size_t row = blockIdx.x;
    const float4* x = (const float4*)(X + row * S_LEN);
    float4*       y = (float4*)(Y + row * S_LEN);
    int tid = threadIdx.x;

    float4 v[4];
    float sum = 0.f;
#pragma unroll
    for (int i = 0; i < 4; i++) {
        float4 t = x[tid + i * 256];
        t.x = fmaxf(t.x, 0.f); t.y = fmaxf(t.y, 0.f);
        t.z = fmaxf(t.z, 0.f); t.w = fmaxf(t.w, 0.f);
        v[i] = t;
        sum += (t.x + t.y) + (t.z + t.w);
    }
    sum = block_reduce(sum, sm);
    float mean = sum * (1.f / (float)S_LEN);

    float ssq = 0.f;
#pragma unroll
    for (int i = 0; i < 4; i++) {
        v[i].x -= mean; v[i].y -= mean; v[i].z -= mean; v[i].w -= mean;
        ssq += v[i].x * v[i].x + v[i].y * v[i].y + v[i].z * v[i].z + v[i].w * v[i].w;
    }
    ssq = block_reduce(ssq, sm);
    float scale = 64.f / (sqrtf(ssq) + 1e-5f);   // n^{1/2}/(||o||+eps), n=4096

    if (Res) {
        const float4* r = (const float4*)(Res + row * S_LEN);
#pragma unroll
        for (int i = 0; i < 4; i++) {
            float4 rv = r[tid + i * 256];
            float4 o;
            o.x = rv.x + v[i].x * scale;
            o.y = rv.y + v[i].y * scale;
            o.z = rv.z + v[i].z * scale;
            o.w = rv.w + v[i].w * scale;
            y[tid + i * 256] = o;
        }
    } else {
#pragma unroll
        for (int i = 0; i < 4; i++) {
            float4 o;
            o.x = v[i].x * scale; o.y = v[i].y * scale;
            o.z = v[i].z * scale; o.w = v[i].w * scale;
            y[tid + i * 256] = o;
        }
    }
}

// ---------------------------------------------------------------------------
// Gate: Tmp[b,h,s] = Bc[b,h,s] * (cumsum_h(D)[b,h,s]/(s+1) + P[b,h,s]) + Sb[b,h,s]
// Threads over (b,s); serial inclusive cumsum over channels (coalesced loads).
// ---------------------------------------------------------------------------
__global__ void gate_kernel(const float* __restrict__ D, const float* __restrict__ P,
                            const float* __restrict__ Sb, const float* __restrict__ Bc,
                            float* __restrict__ Tmp)
{
    int tid = blockIdx.x * blockDim.x + threadIdx.x;     // B*S
    int b = tid >> 12;
    int s = tid & (S_LEN - 1);
    float inv = 1.f / (float)(s + 1);
    float acc = 0.f;
    size_t base = ((size_t)b * HCH) * S_LEN + s;
#pragma unroll 8
    for (int h = 0; h < HCH; h++) {
        size_t i = base + (size_t)h * S_LEN;
        acc += D[i];
        Tmp[i] = Bc[i] * (acc * inv + P[i]) + Sb[i];
    }
}

// ---------------------------------------------------------------------------
// Concat [a; b] over channels into XC (B, 2H, S)
// ---------------------------------------------------------------------------
__global__ void concat_kernel(const float* __restrict__ A, const float* __restrict__ Bc,
                              float* __restrict__ XC)
{
    int idx = blockIdx.x * blockDim.x + threadIdx.x;     // B*512*S
    int s = idx & (S_LEN - 1);
    int c = (idx >> 12) & 511;
    int b = idx >> 21;
    float v = (c < HCH) ? A [((size_t)b * HCH + c) * S_LEN + s]
                        : Bc[((size_t)b * HCH + (c - HCH)) * S_LEN + s];
    XC[idx] = v;
}

// ---------------------------------------------------------------------------
// Per-token NLL with online logsumexp over OUT=256 classes (bias added here)
// ---------------------------------------------------------------------------
__global__ void loss_kernel(const float* __restrict__ logits,
                            const float* __restrict__ outb,
                            const int*   __restrict__ tgt,
                            float* __restrict__ nll)
{
    int tid = blockIdx.x * blockDim.x + threadIdx.x;     // B*S
    int b = tid >> 12;
    int s = tid & (S_LEN - 1);
    const float* lg = logits + ((size_t)b * NOUT) * S_LEN + s;
    int tg = tgt[tid];

    float m = -1e30f, se = 0.f, vt = 0.f;
    for (int o = 0; o < NOUT; o++) {
        float v = lg[(size_t)o * S_LEN] + outb[o];
        if (o == tg) vt = v;
        if (v > m) { se = se * expf(m - v) + 1.f; m = v; }
        else       { se += expf(v - m); }
    }
    nll[tid] = -(vt - m - logf(se));
}

__global__ void reduce_mean_kernel(const float* __restrict__ nll, float* __restrict__ out)
{
    __shared__ float sm[33];
    float v = 0.f;
    for (int i = threadIdx.x; i < BATCH * S_LEN; i += 256) v += nll[i];
    v = block_reduce(v, sm);
    if (threadIdx.x == 0) out[0] = v * (1.f / (float)(BATCH * S_LEN));
}

// ---------------------------------------------------------------------------
// Host orchestration
// ---------------------------------------------------------------------------
extern "C" void kernel_launch(void* const* d_in, const int* in_sizes, int n_in,
                              void* d_out, int out_size)
{
    const float* emb   = (const float*)d_in[0];
    const float* w0    = (const float*)d_in[1];
    const float* w1    = (const float*)d_in[2];
    const float* w2    = (const float*)d_in[3];
    const float* out_w = (const float*)d_in[4];
    const float* out_b = (const float*)d_in[5];
    const int*   inp   = (const int*)d_in[6];
    const int*   tgt   = (const int*)d_in[7];
    float* out = (float*)d_out;

    float *A, *Bc, *O, *T1, *T2, *D, *P, *Sb, *NLL;
    cudaGetSymbolAddress((void**)&A,  g_A);
    cudaGetSymbolAddress((void**)&Bc, g_Bc);
    cudaGetSymbolAddress((void**)&O,  g_O);
    cudaGetSymbolAddress((void**)&T1, g_T1);
    cudaGetSymbolAddress((void**)&T2, g_T2);
    cudaGetSymbolAddress((void**)&D,  g_D);
    cudaGetSymbolAddress((void**)&P,  g_P);
    cudaGetSymbolAddress((void**)&Sb, g_S);
    cudaGetSymbolAddress((void**)&NLL,g_NLL);

    embed_kernel<<<(BATCH * S_LEN) / 256, 256>>>(emb, inp, A, Bc);

    float* pa = A;
    float* pb = Bc;
    for (int l = 0; l < NDEPTH; l++) {
        addpos_kernel<<<(BATCH * HCH * S_LEN) / 256, 256>>>(pb, O);
        for (int j = 0; j < 3; j++) {
            int wi = l * 3 + j;
            const float* cw0 = w0 + (size_t)wi * ICH * HCH;
            const float* cw1 = w1 + (size_t)wi * ICH * ICH * KWIDTH;
            const float* cw2 = w2 + (size_t)wi * HCH * ICH;
            float* dst = (j == 0) ? D : ((j == 1) ? P : Sb);

            conv_gemm<1, 64, 4><<<dim3(S_LEN / 64, ICH / 64, BATCH), 256>>>(O,  cw0, T1, HCH, ICH);
            actnorm_kernel<<<BATCH * ICH, 256>>>(T1, nullptr, T1);
            conv_gemm<7, 128, 8><<<dim3(S_LEN / 128, ICH / 64, BATCH), 256>>>(T1, cw1, T2, ICH, ICH);
            actnorm_kernel<<<BATCH * ICH, 256>>>(T2, nullptr, T2);
            conv_gemm<1, 64, 4><<<dim3(S_LEN / 64, HCH / 64, BATCH), 256>>>(T2, cw2, dst, ICH, HCH);
        }
        gate_kernel<<<(BATCH * S_LEN) / 256, 256>>>(D, P, Sb, pb, O);
        // new_b = old_a + act_norm(tmp), written into pa's buffer; then swap
        actnorm_kernel<<<BATCH * HCH, 256>>>(O, pa, pa);
        float* t = pa; pa = pb; pb = t;
    }

    // logits = out_w @ concat(a, b) + out_b (bias folded into loss)
    concat_kernel<<<(BATCH * 2 * HCH * S_LEN) / 256, 256>>>(pa, pb, T1);
    conv_gemm<1, 64, 4><<<dim3(S_LEN / 64, NOUT / 64, BATCH), 256>>>(T1, out_w, D, 2 * HCH, NOUT);
    loss_kernel<<<(BATCH * S_LEN) / 256, 256>>>(D, out_b, tgt, NLL);
    reduce_mean_kernel<<<1, 256>>>(NLL, out);
}

// round 3
// speedup vs baseline: 3.5036x; 3.5036x over previous
#include <cuda_runtime.h>
#include <cuda_bf16.h>
#include <math.h>
#include <stdint.h>

// ---------------------------------------------------------------------------
// Problem constants (match reference)
// ---------------------------------------------------------------------------
#define S_LEN   4096
#define BATCH   4
#define HCH     256
#define ICH     512
#define NDEPTH  8
#define KWIDTH  7
#define NOUT    256
#define LOGC    6.4798891f   // log(S/2/pi)

// ---------------------------------------------------------------------------
// Scratch (device globals; no cudaMalloc allowed)
// ---------------------------------------------------------------------------
__device__ float g_A  [BATCH*HCH*S_LEN];
__device__ float g_Bc [BATCH*HCH*S_LEN];
__device__ float g_O  [BATCH*HCH*S_LEN];
__device__ float g_T1 [BATCH*ICH*S_LEN];
__device__ float g_T2 [BATCH*ICH*S_LEN];
__device__ float g_D  [BATCH*HCH*S_LEN];
__device__ float g_P  [BATCH*HCH*S_LEN];
__device__ float g_S  [BATCH*HCH*S_LEN];
__device__ float g_NLL[BATCH*S_LEN];

// ---------------------------------------------------------------------------
// Embedding gather
// ---------------------------------------------------------------------------
__global__ void embed_kernel(const float* __restrict__ emb,
                             const int*   __restrict__ inp,
                             float* __restrict__ A, float* __restrict__ Bc)
{
    int tid = blockIdx.x * blockDim.x + threadIdx.x;     // B*S threads
    int b = tid >> 12;
    int s = tid & (S_LEN - 1);
    int tok = inp[tid];
    const float* e = emb + (size_t)tok * (2 * HCH);
    size_t base = ((size_t)b * HCH) * S_LEN + s;
#pragma unroll 4
    for (int h = 0; h < HCH; h++) {
        A [base + (size_t)h * S_LEN] = e[h];
        Bc[base + (size_t)h * S_LEN] = e[HCH + h];
    }
}

// ---------------------------------------------------------------------------
// out = b + pos_embd
// ---------------------------------------------------------------------------
__global__ void addpos_kernel(const float* __restrict__ Bc, float* __restrict__ O)
{
    int idx = blockIdx.x * blockDim.x + threadIdx.x;     // B*H*S
    int s = idx & (S_LEN - 1);
    int h = (idx >> 12) & (HCH - 1);
    float feat = (float)(h + 1);
    float additive = (float)((h + 1) & 1);
    float fe0 = (feat - additive) * 0.5f * (8.0f / (float)HCH) - LOGC;
    float fe  = expf(fe0) + additive * 3.14159265358979f;
    float pe  = sinf((float)(s + 1) * fe) * 0.125f;
    O[idx] = Bc[idx] + pe;
}

// ---------------------------------------------------------------------------
// cp.async helper (16B, src-size 0 => zero-fill, no global access)
// ---------------------------------------------------------------------------
__device__ __forceinline__ void cp16(uint32_t saddr, const void* gaddr, bool pred)
{
    int sz = pred ? 16 : 0;
    asm volatile("cp.async.cg.shared.global [%0], [%1], 16, %2;\n"
                 :: "r"(saddr), "l"(gaddr), "r"(sz));
}
__device__ __forceinline__ void cp_commit()
{
    asm volatile("cp.async.commit_group;\n" ::: "memory");
}
template<int N>
__device__ __forceinline__ void cp_wait()
{
    asm volatile("cp.async.wait_group %0;\n" :: "n"(N) : "memory");
}

// ---------------------------------------------------------------------------
// Tensor-core causal-conv / GEMM (tf32 mma.sync.m16n8k8).
//   Y[b,o,s] = sum_ci sum_k W[o,ci,k] * X[b,ci,s-(KW-1)+k]   (zero left pad)
// CTA tile: 128 out x 128 seq. 8 warps = 2(M) x 4(N), warp tile 64 x 32.
// K pipeline: 16 cin per stage, 2-stage cp.async double buffer.
// ---------------------------------------------------------------------------
template<int KW>
__global__ void __launch_bounds__(256, 1)
mma_conv(const float* __restrict__ X, const float* __restrict__ W,
         float* __restrict__ Y, int Cin, int Cout)
{
    constexpr int TM = 128, TN = 128, TK = 16;
    constexpr int SHIFT = (KW > 1) ? 8 : 0;        // aligned halo lead-in
    constexpr int XW   = TN + SHIFT;               // loaded width per ci row
    constexpr int XSTR = TN + 8;                   // 136: bank-safe stride
    constexpr int WROW = TK * KW;                  // contiguous gmem floats per o
    constexpr int WSTR = WROW + 4;                 // 116 / 20: bank-safe, 16B-mult
    constexpr int XV   = XW / 4;                   // vec4 per ci row
    constexpr int WV   = WROW / 4;                 // vec4 per o row

    extern __shared__ float smem[];
    float* Xs = smem;                              // [2][TK][XSTR]
    float* Ws = smem + 2 * TK * XSTR;              // [2][TM][WSTR]

    const int s0 = blockIdx.x * TN;
    const int o0 = blockIdx.y * TM;
    const int bb = blockIdx.z;
    const float* Xb = X + (size_t)bb * Cin * S_LEN;
    float*       Yb = Y + (size_t)bb * Cout * S_LEN;

    const int tid   = threadIdx.x;
    const int lane  = tid & 31;
    const int wid   = tid >> 5;
    const int warpM = wid >> 2;                    // 0..1
    const int warpN = wid & 3;                     // 0..3
    const int gid   = lane >> 2;                   // 0..7
    const int tig   = lane & 3;                    // 0..3

    const uint32_t xs_base = (uint32_t)__cvta_generic_to_shared(Xs);
    const uint32_t ws_base = (uint32_t)__cvta_generic_to_shared(Ws);

    const int NT = Cin / TK;

    // stage loader (all 256 threads convergent; commit is uniform)
    auto load_stage = [&](int it, int buf) {
        int ci0 = it * TK;
        // X tile: TK rows x XW floats, starting at s0-SHIFT (zfill OOB)
        for (int i = tid; i < TK * XV; i += 256) {
            int ci = i / XV;
            int v  = i - ci * XV;
            int sg = s0 - SHIFT + v * 4;
            const float* gp = Xb + (size_t)(ci0 + ci) * S_LEN + sg;
            uint32_t sa = xs_base + (uint32_t)(((buf * TK + ci) * XSTR + v * 4) * 4);
            cp16(sa, gp, sg >= 0);
        }
        // W tile: TM rows x WROW floats (contiguous per o)
        for (int i = tid; i < TM * WV; i += 256) {
            int o = i / WV;
            int v = i - o * WV;
            const float* gp = W + (size_t)(o0 + o) * Cin * KW + (size_t)ci0 * KW + v * 4;
            uint32_t sa = ws_base + (uint32_t)(((buf * TM + o) * WSTR + v * 4) * 4);
            cp16(sa, gp, true);
        }
        cp_commit();
    };

    float acc[4][4][4];
#pragma unroll
    for (int mi = 0; mi < 4; mi++)
#pragma unroll
        for (int ni = 0; ni < 4; ni++)
#pragma unroll
            for (int r = 0; r < 4; r++) acc[mi][ni][r] = 0.f;

    load_stage(0, 0);

    for (int it = 0; it < NT; it++) {
        int buf = it & 1;
        if (it + 1 < NT) load_stage(it + 1, buf ^ 1);
        if (it + 1 < NT) cp_wait<1>(); else cp_wait<0>();
        __syncthreads();

        const uint32_t* Wt = (const uint32_t*)(Ws + buf * TM * WSTR);
        const uint32_t* Xt = (const uint32_t*)(Xs + buf * TK * XSTR);

#pragma unroll
        for (int k = 0; k < KW; k++) {
#pragma unroll
            for (int ks = 0; ks < 2; ks++) {
                const int colk = ks * 8 + tig;     // K index within 16-tile
                uint32_t Af[4][4];
#pragma unroll
                for (int mi = 0; mi < 4; mi++) {
                    const uint32_t* w0p = Wt + (warpM * 64 + mi * 16 + gid) * WSTR + colk * KW + k;
                    Af[mi][0] = w0p[0];
                    Af[mi][1] = w0p[8 * WSTR];
                    Af[mi][2] = w0p[4 * KW];
                    Af[mi][3] = w0p[8 * WSTR + 4 * KW];
                }
                uint32_t Bf[4][2];
                const int tofs = SHIFT - KW + 1 + k;
#pragma unroll
                for (int ni = 0; ni < 4; ni++) {
                    const uint32_t* xp = Xt + colk * XSTR + warpN * 32 + ni * 8 + gid + tofs;
                    Bf[ni][0] = xp[0];
                    Bf[ni][1] = xp[4 * XSTR];
                }
#pragma unroll
                for (int mi = 0; mi < 4; mi++)
#pragma unroll
                    for (int ni = 0; ni < 4; ni++) {
                        float* d = acc[mi][ni];
                        asm volatile(
                            "mma.sync.aligned.m16n8k8.row.col.f32.tf32.tf32.f32 "
                            "{%0,%1,%2,%3}, {%4,%5,%6,%7}, {%8,%9}, {%0,%1,%2,%3};\n"
                            : "+f"(d[0]), "+f"(d[1]), "+f"(d[2]), "+f"(d[3])
                            : "r"(Af[mi][0]), "r"(Af[mi][1]), "r"(Af[mi][2]), "r"(Af[mi][3]),
                              "r"(Bf[ni][0]), "r"(Bf[ni][1]));
                    }
            }
        }
        __syncthreads();
    }

    // epilogue: write fp32
#pragma unroll
    for (int mi = 0; mi < 4; mi++) {
        int o = o0 + warpM * 64 + mi * 16 + gid;
#pragma unroll
        for (int ni = 0; ni < 4; ni++) {
            int s = s0 + warpN * 32 + ni * 8 + 2 * tig;
            float2 v0 = make_float2(acc[mi][ni][0], acc[mi][ni][1]);
            float2 v1 = make_float2(acc[mi][ni][2], acc[mi][ni][3]);
            *(float2*)&Yb[(size_t)o * S_LEN + s]       = v0;
            *(float2*)&Yb[(size_t)(o + 8) * S_LEN + s] = v1;
        }
    }
}

// ---------------------------------------------------------------------------
// Block reduction helper (256 threads = 8 warps)
// ---------------------------------------------------------------------------
__device__ __forceinline__ float block_reduce(float v, float* sm)
{
    int lane = threadIdx.x & 31;
    int w    = threadIdx.x >> 5;
#pragma unroll
    for (int o = 16; o > 0; o >>= 1) v += __shfl_xor_sync(0xffffffffu, v, o);
    if (lane == 0) sm[w] = v;
    __syncthreads();
    if (w == 0) {
        float r = (lane < 8) ? sm[lane] : 0.f;
#pragma unroll
        for (int o = 4; o > 0; o >>= 1) r += __shfl_xor_sync(0xffffffffu, r, o);
        if (lane == 0) sm[32] = r;
    }
    __syncthreads();
    float out = sm[32];
    __syncthreads();
    return out;
}

// ---------------------------------------------------------------------------
// act_norm over the sequence axis; optional fused residual add.
// ---------------------------------------------------------------------------
__global__ void actnorm_kernel(const float* __restrict__ X,
                               const float* __restrict__ Res,
                               float* __restrict__ Y)
{
    __shared__ float sm[33];
    size_t row = blockIdx.x;
    const float4* x = (const float4*)(X + row * S_LEN);
    float4*       y = (float4*)(Y + row * S_LEN);
    int tid = threadIdx.x;

    float4 v[4];
    float sum = 0.f;
#pragma unroll
    for (int i = 0; i < 4; i++) {
        float4 t = x[tid + i * 256];
        t.x = fmaxf(t.x, 0.f); t.y = fmaxf(t.y, 0.f);
        t.z = fmaxf(t.z, 0.f); t.w = fmaxf(t.w, 0.f);
        v[i] = t;
        sum += (t.x + t.y) + (t.z + t.w);
    }
    sum = block_reduce(sum, sm);
    float mean = sum * (1.f / (float)S_LEN);

    float ssq = 0.f;
#pragma unroll
    for (int i = 0; i < 4; i++) {
        v[i].x -= mean; v[i].y -= mean; v[i].z -= mean; v[i].w -= mean;
        ssq += v[i].x * v[i].x + v[i].y * v[i].y + v[i].z * v[i].z + v[i].w * v[i].w;
    }
    ssq = block_reduce(ssq, sm);
    float scale = 64.f / (sqrtf(ssq) + 1e-5f);

    if (Res) {
        const float4* r = (const float4*)(Res + row * S_LEN);
#pragma unroll
        for (int i = 0; i < 4; i++) {
            float4 rv = r[tid + i * 256];
            float4 o;
            o.x = rv.x + v[i].x * scale;
            o.y = rv.y + v[i].y * scale;
            o.z = rv.z + v[i].z * scale;
            o.w = rv.w + v[i].w * scale;
            y[tid + i * 256] = o;
        }
    } else {
#pragma unroll
        for (int i = 0; i < 4; i++) {
            float4 o;
            o.x = v[i].x * scale; o.y = v[i].y * scale;
            o.z = v[i].z * scale; o.w = v[i].w * scale;
            y[tid + i * 256] = o;
        }
    }
}

// ---------------------------------------------------------------------------
// Gate: Tmp = Bc * (cumsum_h(D)/(s+1) + P) + Sb
// ---------------------------------------------------------------------------
__global__ void gate_kernel(const float* __restrict__ D, const float* __restrict__ P,
                            const float* __restrict__ Sb, const float* __restrict__ Bc,
                            float* __restrict__ Tmp)
{
    int tid = blockIdx.x * blockDim.x + threadIdx.x;     // B*S
    int b = tid >> 12;
    int s = tid & (S_LEN - 1);
    float inv = 1.f / (float)(s + 1);
    float acc = 0.f;
    size_t base = ((size_t)b * HCH) * S_LEN + s;
#pragma unroll 8
    for (int h = 0; h < HCH; h++) {
        size_t i = base + (size_t)h * S_LEN;
        acc += D[i];
        Tmp[i] = Bc[i] * (acc * inv + P[i]) + Sb[i];
    }
}

// ---------------------------------------------------------------------------
// Concat [a; b] over channels
// ---------------------------------------------------------------------------
__global__ void concat_kernel(const float* __restrict__ A, const float* __restrict__ Bc,
                              float* __restrict__ XC)
{
    int idx = blockIdx.x * blockDim.x + threadIdx.x;     // B*512*S
    int s = idx & (S_LEN - 1);
    int c = (idx >> 12) & 511;
    int b = idx >> 21;
    float v = (c < HCH) ? A [((size_t)b * HCH + c) * S_LEN + s]
                        : Bc[((size_t)b * HCH + (c - HCH)) * S_LEN + s];
    XC[idx] = v;
}

// ---------------------------------------------------------------------------
// Per-token NLL (online logsumexp) + deterministic mean
// ---------------------------------------------------------------------------
__global__ void loss_kernel(const float* __restrict__ logits,
                            const float* __restrict__ outb,
                            const int*   __restrict__ tgt,
                            float* __restrict__ nll)
{
    int tid = blockIdx.x * blockDim.x + threadIdx.x;     // B*S
    int b = tid >> 12;
    int s = tid & (S_LEN - 1);
    const float* lg = logits + ((size_t)b * NOUT) * S_LEN + s;
    int tg = tgt[tid];

    float m = -1e30f, se = 0.f, vt = 0.f;
    for (int o = 0; o < NOUT; o++) {
        float v = lg[(size_t)o * S_LEN] + outb[o];
        if (o == tg) vt = v;
        if (v > m) { se = se * expf(m - v) + 1.f; m = v; }
        else       { se += expf(v - m); }
    }
    nll[tid] = -(vt - m - logf(se));
}

__global__ void reduce_mean_kernel(const float* __restrict__ nll, float* __restrict__ out)
{
    __shared__ float sm[33];
    float v = 0.f;
    for (int i = threadIdx.x; i < BATCH * S_LEN; i += 256) v += nll[i];
    v = block_reduce(v, sm);
    if (threadIdx.x == 0) out[0] = v * (1.f / (float)(BATCH * S_LEN));
}

// ---------------------------------------------------------------------------
// Host orchestration
// ---------------------------------------------------------------------------
static const int SMEM7 = (2 * 16 * 136 + 2 * 128 * (16 * 7 + 4)) * 4;  // 136192 B
static const int SMEM1 = (2 * 16 * 136 + 2 * 128 * (16 * 1 + 4)) * 4;  //  37888 B

extern "C" void kernel_launch(void* const* d_in, const int* in_sizes, int n_in,
                              void* d_out, int out_size)
{
    const float* emb   = (const float*)d_in[0];
    const float* w0    = (const float*)d_in[1];
    const float* w1    = (const float*)d_in[2];
    const float* w2    = (const float*)d_in[3];
    const float* out_w = (const float*)d_in[4];
    const float* out_b = (const float*)d_in[5];
    const int*   inp   = (const int*)d_in[6];
    const int*   tgt   = (const int*)d_in[7];
    float* out = (float*)d_out;

    float *A, *Bc, *O, *T1, *T2, *D, *P, *Sb, *NLL;
    cudaGetSymbolAddress((void**)&A,  g_A);
    cudaGetSymbolAddress((void**)&Bc, g_Bc);
    cudaGetSymbolAddress((void**)&O,  g_O);
    cudaGetSymbolAddress((void**)&T1, g_T1);
    cudaGetSymbolAddress((void**)&T2, g_T2);
    cudaGetSymbolAddress((void**)&D,  g_D);
    cudaGetSymbolAddress((void**)&P,  g_P);
    cudaGetSymbolAddress((void**)&Sb, g_S);
    cudaGetSymbolAddress((void**)&NLL,g_NLL);

    cudaFuncSetAttribute(mma_conv<7>, cudaFuncAttributeMaxDynamicSharedMemorySize, SMEM7);
    cudaFuncSetAttribute(mma_conv<1>, cudaFuncAttributeMaxDynamicSharedMemorySize, SMEM1);

    embed_kernel<<<(BATCH * S_LEN) / 256, 256>>>(emb, inp, A, Bc);

    float* pa = A;
    float* pb = Bc;
    for (int l = 0; l < NDEPTH; l++) {
        addpos_kernel<<<(BATCH * HCH * S_LEN) / 256, 256>>>(pb, O);
        for (int j = 0; j < 3; j++) {
            int wi = l * 3 + j;
            const float* cw0 = w0 + (size_t)wi * ICH * HCH;
            const float* cw1 = w1 + (size_t)wi * ICH * ICH * KWIDTH;
            const float* cw2 = w2 + (size_t)wi * HCH * ICH;
            float* dst = (j == 0) ? D : ((j == 1) ? P : Sb);

            mma_conv<1><<<dim3(S_LEN / 128, ICH / 128, BATCH), 256, SMEM1>>>(O,  cw0, T1, HCH, ICH);
            actnorm_kernel<<<BATCH * ICH, 256>>>(T1, nullptr, T1);
            mma_conv<7><<<dim3(S_LEN / 128, ICH / 128, BATCH), 256, SMEM7>>>(T1, cw1, T2, ICH, ICH);
            actnorm_kernel<<<BATCH * ICH, 256>>>(T2, nullptr, T2);
            mma_conv<1><<<dim3(S_LEN / 128, HCH / 128, BATCH), 256, SMEM1>>>(T2, cw2, dst, ICH, HCH);
        }
        gate_kernel<<<(BATCH * S_LEN) / 256, 256>>>(D, P, Sb, pb, O);
        actnorm_kernel<<<BATCH * HCH, 256>>>(O, pa, pa);
        float* t = pa; pa = pb; pb = t;
    }

    concat_kernel<<<(BATCH * 2 * HCH * S_LEN) / 256, 256>>>(pa, pb, T1);
    mma_conv<1><<<dim3(S_LEN / 128, NOUT / 128, BATCH), 256, SMEM1>>>(T1, out_w, D, 2 * HCH, NOUT);
    loss_kernel<<<(BATCH * S_LEN) / 256, 256>>>(D, out_b, tgt, NLL);
    reduce_mean_kernel<<<1, 256>>>(NLL, out);
}

// round 6
// speedup vs baseline: 3.5537x; 1.0143x over previous
#include <cuda_runtime.h>
#include <cuda_bf16.h>
#include <math.h>
#include <stdint.h>

// ---------------------------------------------------------------------------
// Problem constants (match reference)
// ---------------------------------------------------------------------------
#define S_LEN   4096
#define BATCH   4
#define HCH     256
#define ICH     512
#define NDEPTH  8
#define KWIDTH  7
#define NOUT    256
#define LOGC    6.4798891f   // log(S/2/pi)

// ---------------------------------------------------------------------------
// Scratch (device globals; no cudaMalloc allowed)
// ---------------------------------------------------------------------------
__device__ float g_A  [BATCH*HCH*S_LEN];
__device__ float g_Bc [BATCH*HCH*S_LEN];
__device__ float g_O  [BATCH*HCH*S_LEN];
__device__ float g_T1 [BATCH*ICH*S_LEN];
__device__ float g_T2 [BATCH*ICH*S_LEN];
__device__ float g_D  [BATCH*HCH*S_LEN];
__device__ float g_P  [BATCH*HCH*S_LEN];
__device__ float g_S  [BATCH*HCH*S_LEN];
__device__ float g_NLL[BATCH*S_LEN];

// ---------------------------------------------------------------------------
// Tiny init launch (also aligns ncu -s 5 -c 1 onto mma_conv<7> at launch #6)
// ---------------------------------------------------------------------------
__global__ void init_kernel(float* __restrict__ nll)
{
    int i = blockIdx.x * blockDim.x + threadIdx.x;
    if (i < BATCH * S_LEN) nll[i] = 0.f;
}

// ---------------------------------------------------------------------------
// Embedding gather
// ---------------------------------------------------------------------------
__global__ void embed_kernel(const float* __restrict__ emb,
                             const int*   __restrict__ inp,
                             float* __restrict__ A, float* __restrict__ Bc)
{
    int tid = blockIdx.x * blockDim.x + threadIdx.x;     // B*S threads
    int b = tid >> 12;
    int s = tid & (S_LEN - 1);
    int tok = inp[tid];
    const float* e = emb + (size_t)tok * (2 * HCH);
    size_t base = ((size_t)b * HCH) * S_LEN + s;
#pragma unroll 4
    for (int h = 0; h < HCH; h++) {
        A [base + (size_t)h * S_LEN] = e[h];
        Bc[base + (size_t)h * S_LEN] = e[HCH + h];
    }
}

// ---------------------------------------------------------------------------
// out = b + pos_embd
// ---------------------------------------------------------------------------
__global__ void addpos_kernel(const float* __restrict__ Bc, float* __restrict__ O)
{
    int idx = blockIdx.x * blockDim.x + threadIdx.x;     // B*H*S
    int s = idx & (S_LEN - 1);
    int h = (idx >> 12) & (HCH - 1);
    float feat = (float)(h + 1);
    float additive = (float)((h + 1) & 1);
    float fe0 = (feat - additive) * 0.5f * (8.0f / (float)HCH) - LOGC;
    float fe  = expf(fe0) + additive * 3.14159265358979f;
    float pe  = sinf((float)(s + 1) * fe) * 0.125f;
    O[idx] = Bc[idx] + pe;
}

// ---------------------------------------------------------------------------
// cp.async helper (16B, src-size 0 => zero-fill)
// ---------------------------------------------------------------------------
__device__ __forceinline__ void cp16(uint32_t saddr, const void* gaddr, bool pred)
{
    int sz = pred ? 16 : 0;
    asm volatile("cp.async.cg.shared.global [%0], [%1], 16, %2;\n"
                 :: "r"(saddr), "l"(gaddr), "r"(sz));
}
__device__ __forceinline__ void cp_commit()
{
    asm volatile("cp.async.commit_group;\n" ::: "memory");
}
template<int N>
__device__ __forceinline__ void cp_wait()
{
    asm volatile("cp.async.wait_group %0;\n" :: "n"(N) : "memory");
}

// ---------------------------------------------------------------------------
// Tensor-core causal-conv / GEMM (tf32 mma.sync.m16n8k8).
//   Y[b,o,s] = sum_ci sum_k W[o,ci,k] * X[b,ci,s-(KW-1)+k]   (zero left pad)
// CTA tile: 128 out x 128 seq. 8 warps = 2(M) x 4(N), warp tile 64 x 32.
// K pipeline: 16 cin per stage, 3-stage cp.async ring buffer.
// ---------------------------------------------------------------------------
template<int KW>
__global__ void __launch_bounds__(256, 1)
mma_conv(const float* __restrict__ X, const float* __restrict__ W,
         float* __restrict__ Y, int Cin, int Cout)
{
    constexpr int NSTG = 3;
    constexpr int TM = 128, TN = 128, TK = 16;
    constexpr int SHIFT = (KW > 1) ? 8 : 0;        // aligned halo lead-in
    constexpr int XW   = TN + SHIFT;               // loaded width per ci row
    constexpr int XSTR = TN + 8;                   // 136: bank-safe stride
    constexpr int WROW = TK * KW;                  // contiguous gmem floats per o
    constexpr int WSTR = WROW + 4;                 // 116 / 20: bank-safe, 16B-mult
    constexpr int XV   = XW / 4;                   // vec4 per ci row
    constexpr int WV   = WROW / 4;                 // vec4 per o row

    extern __shared__ float smem[];
    float* Xs = smem;                              // [NSTG][TK][XSTR]
    float* Ws = smem + NSTG * TK * XSTR;           // [NSTG][TM][WSTR]

    const int s0 = blockIdx.x * TN;
    const int o0 = blockIdx.y * TM;
    const int bb = blockIdx.z;
    const float* Xb = X + (size_t)bb * Cin * S_LEN;
    float*       Yb = Y + (size_t)bb * Cout * S_LEN;

    const int tid   = threadIdx.x;
    const int lane  = tid & 31;
    const int wid   = tid >> 5;
    const int warpM = wid >> 2;                    // 0..1
    const int warpN = wid & 3;                     // 0..3
    const int gid   = lane >> 2;                   // 0..7
    const int tig   = lane & 3;                    // 0..3

    const uint32_t xs_base = (uint32_t)__cvta_generic_to_shared(Xs);
    const uint32_t ws_base = (uint32_t)__cvta_generic_to_shared(Ws);

    const int NT = Cin / TK;                       // >= 16 always

    // stage loader (all 256 threads convergent; commit is uniform)
    auto load_stage = [&](int it, int buf) {
        int ci0 = it * TK;
        // X tile: TK rows x XW floats, starting at s0-SHIFT (zfill OOB)
        for (int i = tid; i < TK * XV; i += 256) {
            int ci = i / XV;
            int v  = i - ci * XV;
            int sg = s0 - SHIFT + v * 4;
            const float* gp = Xb + (size_t)(ci0 + ci) * S_LEN + sg;
            uint32_t sa = xs_base + (uint32_t)(((buf * TK + ci) * XSTR + v * 4) * 4);
            cp16(sa, gp, sg >= 0);
        }
        // W tile: TM rows x WROW floats (contiguous per o)
        for (int i = tid; i < TM * WV; i += 256) {
            int o = i / WV;
            int v = i - o * WV;
            const float* gp = W + (size_t)(o0 + o) * Cin * KW + (size_t)ci0 * KW + v * 4;
            uint32_t sa = ws_base + (uint32_t)(((buf * TM + o) * WSTR + v * 4) * 4);
            cp16(sa, gp, true);
        }
        cp_commit();
    };

    float acc[4][4][4];
#pragma unroll
    for (int mi = 0; mi < 4; mi++)
#pragma unroll
        for (int ni = 0; ni < 4; ni++)
#pragma unroll
            for (int r = 0; r < 4; r++) acc[mi][ni][r] = 0.f;

    // prologue: fill 2 of 3 stages
    load_stage(0, 0);
    load_stage(1, 1);

    int buf = 0;                                   // stage being consumed
    int nbuf = 2;                                  // stage to fill next
    for (int it = 0; it < NT; it++) {
        if (it + 2 < NT) {
            load_stage(it + 2, nbuf);
            if (++nbuf == NSTG) nbuf = 0;
        }
        // ensure stage `it` is complete: allow pending prefetches only
        if (it + 2 < NT)      cp_wait<2>();
        else if (it + 1 < NT) cp_wait<1>();
        else                  cp_wait<0>();
        __syncthreads();

        const uint32_t* Wt = (const uint32_t*)(Ws + buf * TM * WSTR);
        const uint32_t* Xt = (const uint32_t*)(Xs + buf * TK * XSTR);

#pragma unroll
        for (int k = 0; k < KW; k++) {
#pragma unroll
            for (int ks = 0; ks < 2; ks++) {
                const int colk = ks * 8 + tig;     // K index within 16-tile
                uint32_t Af[4][4];
#pragma unroll
                for (int mi = 0; mi < 4; mi++) {
                    const uint32_t* w0p = Wt + (warpM * 64 + mi * 16 + gid) * WSTR + colk * KW + k;
                    Af[mi][0] = w0p[0];
                    Af[mi][1] = w0p[8 * WSTR];
                    Af[mi][2] = w0p[4 * KW];
                    Af[mi][3] = w0p[8 * WSTR + 4 * KW];
                }
                uint32_t Bf[4][2];
                const int tofs = SHIFT - KW + 1 + k;
#pragma unroll
                for (int ni = 0; ni < 4; ni++) {
                    const uint32_t* xp = Xt + colk * XSTR + warpN * 32 + ni * 8 + gid + tofs;
                    Bf[ni][0] = xp[0];
                    Bf[ni][1] = xp[4 * XSTR];
                }
#pragma unroll
                for (int mi = 0; mi < 4; mi++)
#pragma unroll
                    for (int ni = 0; ni < 4; ni++) {
                        float* d = acc[mi][ni];
                        asm volatile(
                            "mma.sync.aligned.m16n8k8.row.col.f32.tf32.tf32.f32 "
                            "{%0,%1,%2,%3}, {%4,%5,%6,%7}, {%8,%9}, {%0,%1,%2,%3};\n"
                            : "+f"(d[0]), "+f"(d[1]), "+f"(d[2]), "+f"(d[3])
                            : "r"(Af[mi][0]), "r"(Af[mi][1]), "r"(Af[mi][2]), "r"(Af[mi][3]),
                              "r"(Bf[ni][0]), "r"(Bf[ni][1]));
                    }
            }
        }
        __syncthreads();
        if (++buf == NSTG) buf = 0;
    }

    // epilogue: write fp32
#pragma unroll
    for (int mi = 0; mi < 4; mi++) {
        int o = o0 + warpM * 64 + mi * 16 + gid;
#pragma unroll
        for (int ni = 0; ni < 4; ni++) {
            int s = s0 + warpN * 32 + ni * 8 + 2 * tig;
            float2 v0 = make_float2(acc[mi][ni][0], acc[mi][ni][1]);
            float2 v1 = make_float2(acc[mi][ni][2], acc[mi][ni][3]);
            *(float2*)&Yb[(size_t)o * S_LEN + s]       = v0;
            *(float2*)&Yb[(size_t)(o + 8) * S_LEN + s] = v1;
        }
    }
}

// ---------------------------------------------------------------------------
// Block reduction helper (256 threads = 8 warps)
// ---------------------------------------------------------------------------
__device__ __forceinline__ float block_reduce(float v, float* sm)
{
    int lane = threadIdx.x & 31;
    int w    = threadIdx.x >> 5;
#pragma unroll
    for (int o = 16; o > 0; o >>= 1) v += __shfl_xor_sync(0xffffffffu, v, o);
    if (lane == 0) sm[w] = v;
    __syncthreads();
    if (w == 0) {
        float r = (lane < 8) ? sm[lane] : 0.f;
#pragma unroll
        for (int o = 4; o > 0; o >>= 1) r += __shfl_xor_sync(0xffffffffu, r, o);
        if (lane == 0) sm[32] = r;
    }
    __syncthreads();
    float out = sm[32];
    __syncthreads();
    return out;
}

// ---------------------------------------------------------------------------
// act_norm over the sequence axis; optional fused residual add.
// ---------------------------------------------------------------------------
__global__ void actnorm_kernel(const float* __restrict__ X,
                               const float* __restrict__ Res,
                               float* __restrict__ Y)
{
    __shared__ float sm[33];
    size_t row = blockIdx.x;
    const float4* x = (const float4*)(X + row * S_LEN);
    float4*       y = (float4*)(Y + row * S_LEN);
    int tid = threadIdx.x;

    float4 v[4];
    float sum = 0.f;
#pragma unroll
    for (int i = 0; i < 4; i++) {
        float4 t = x[tid + i * 256];
        t.x = fmaxf(t.x, 0.f); t.y = fmaxf(t.y, 0.f);
        t.z = fmaxf(t.z, 0.f); t.w = fmaxf(t.w, 0.f);
        v[i] = t;
        sum += (t.x + t.y) + (t.z + t.w);
    }
    sum = block_reduce(sum, sm);
    float mean = sum * (1.f / (float)S_LEN);

    float ssq = 0.f;
#pragma unroll
    for (int i = 0; i < 4; i++) {
        v[i].x -= mean; v[i].y -= mean; v[i].z -= mean; v[i].w -= mean;
        ssq += v[i].x * v[i].x + v[i].y * v[i].y + v[i].z * v[i].z + v[i].w * v[i].w;
    }
    ssq = block_reduce(ssq, sm);
    float scale = 64.f / (sqrtf(ssq) + 1e-5f);

    if (Res) {
        const float4* r = (const float4*)(Res + row * S_LEN);
#pragma unroll
        for (int i = 0; i < 4; i++) {
            float4 rv = r[tid + i * 256];
            float4 o;
            o.x = rv.x + v[i].x * scale;
            o.y = rv.y + v[i].y * scale;
            o.z = rv.z + v[i].z * scale;
            o.w = rv.w + v[i].w * scale;
            y[tid + i * 256] = o;
        }
    } else {
#pragma unroll
        for (int i = 0; i < 4; i++) {
            float4 o;
            o.x = v[i].x * scale; o.y = v[i].y * scale;
            o.z = v[i].z * scale; o.w = v[i].w * scale;
            y[tid + i * 256] = o;
        }
    }
}

// ---------------------------------------------------------------------------
// Gate: Tmp = Bc * (cumsum_h(D)/(s+1) + P) + Sb
// ---------------------------------------------------------------------------
__global__ void gate_kernel(const float* __restrict__ D, const float* __restrict__ P,
                            const float* __restrict__ Sb, const float* __restrict__ Bc,
                            float* __restrict__ Tmp)
{
    int tid = blockIdx.x * blockDim.x + threadIdx.x;     // B*S
    int b = tid >> 12;
    int s = tid & (S_LEN - 1);
    float inv = 1.f / (float)(s + 1);
    float acc = 0.f;
    size_t base = ((size_t)b * HCH) * S_LEN + s;
#pragma unroll 8
    for (int h = 0; h < HCH; h++) {
        size_t i = base + (size_t)h * S_LEN;
        acc += D[i];
        Tmp[i] = Bc[i] * (acc * inv + P[i]) + Sb[i];
    }
}

// ---------------------------------------------------------------------------
// Concat [a; b] over channels
// ---------------------------------------------------------------------------
__global__ void concat_kernel(const float* __restrict__ A, const float* __restrict__ Bc,
                              float* __restrict__ XC)
{
    int idx = blockIdx.x * blockDim.x + threadIdx.x;     // B*512*S
    int s = idx & (S_LEN - 1);
    int c = (idx >> 12) & 511;
    int b = idx >> 21;
    float v = (c < HCH) ? A [((size_t)b * HCH + c) * S_LEN + s]
                        : Bc[((size_t)b * HCH + (c - HCH)) * S_LEN + s];
    XC[idx] = v;
}

// ---------------------------------------------------------------------------
// Per-token NLL (online logsumexp) + deterministic mean
// ---------------------------------------------------------------------------
__global__ void loss_kernel(const float* __restrict__ logits,
                            const float* __restrict__ outb,
                            const int*   __restrict__ tgt,
                            float* __restrict__ nll)
{
    int tid = blockIdx.x * blockDim.x + threadIdx.x;     // B*S
    int b = tid >> 12;
    int s = tid & (S_LEN - 1);
    const float* lg = logits + ((size_t)b * NOUT) * S_LEN + s;
    int tg = tgt[tid];

    float m = -1e30f, se = 0.f, vt = 0.f;
    for (int o = 0; o < NOUT; o++) {
        float v = lg[(size_t)o * S_LEN] + outb[o];
        if (o == tg) vt = v;
        if (v > m) { se = se * expf(m - v) + 1.f; m = v; }
        else       { se += expf(v - m); }
    }
    nll[tid] = -(vt - m - logf(se));
}

__global__ void reduce_mean_kernel(const float* __restrict__ nll, float* __restrict__ out)
{
    __shared__ float sm[33];
    float v = 0.f;
    for (int i = threadIdx.x; i < BATCH * S_LEN; i += 256) v += nll[i];
    v = block_reduce(v, sm);
    if (threadIdx.x == 0) out[0] = v * (1.f / (float)(BATCH * S_LEN));
}

// ---------------------------------------------------------------------------
// Host orchestration
// ---------------------------------------------------------------------------
static const int SMEM7 = (3 * 16 * 136 + 3 * 128 * (16 * 7 + 4)) * 4;  // 204288 B
static const int SMEM1 = (3 * 16 * 136 + 3 * 128 * (16 * 1 + 4)) * 4;  //  56832 B

extern "C" void kernel_launch(void* const* d_in, const int* in_sizes, int n_in,
                              void* d_out, int out_size)
{
    const float* emb   = (const float*)d_in[0];
    const float* w0    = (const float*)d_in[1];
    const float* w1    = (const float*)d_in[2];
    const float* w2    = (const float*)d_in[3];
    const float* out_w = (const float*)d_in[4];
    const float* out_b = (const float*)d_in[5];
    const int*   inp   = (const int*)d_in[6];
    const int*   tgt   = (const int*)d_in[7];
    float* out = (float*)d_out;

    float *A, *Bc, *O, *T1, *T2, *D, *P, *Sb, *NLL;
    cudaGetSymbolAddress((void**)&A,  g_A);
    cudaGetSymbolAddress((void**)&Bc, g_Bc);
    cudaGetSymbolAddress((void**)&O,  g_O);
    cudaGetSymbolAddress((void**)&T1, g_T1);
    cudaGetSymbolAddress((void**)&T2, g_T2);
    cudaGetSymbolAddress((void**)&D,  g_D);
    cudaGetSymbolAddress((void**)&P,  g_P);
    cudaGetSymbolAddress((void**)&Sb, g_S);
    cudaGetSymbolAddress((void**)&NLL,g_NLL);

    cudaFuncSetAttribute(mma_conv<7>, cudaFuncAttributeMaxDynamicSharedMemorySize, SMEM7);
    cudaFuncSetAttribute(mma_conv<1>, cudaFuncAttributeMaxDynamicSharedMemorySize, SMEM1);

    // launch #1: init (aligns ncu -s 5 onto mma_conv<7> at launch #6)
    init_kernel<<<(BATCH * S_LEN + 255) / 256, 256>>>(NLL);
    embed_kernel<<<(BATCH * S_LEN) / 256, 256>>>(emb, inp, A, Bc);

    float* pa = A;
    float* pb = Bc;
    for (int l = 0; l < NDEPTH; l++) {
        addpos_kernel<<<(BATCH * HCH * S_LEN) / 256, 256>>>(pb, O);
        for (int j = 0; j < 3; j++) {
            int wi = l * 3 + j;
            const float* cw0 = w0 + (size_t)wi * ICH * HCH;
            const float* cw1 = w1 + (size_t)wi * ICH * ICH * KWIDTH;
            const float* cw2 = w2 + (size_t)wi * HCH * ICH;
            float* dst = (j == 0) ? D : ((j == 1) ? P : Sb);

            mma_conv<1><<<dim3(S_LEN / 128, ICH / 128, BATCH), 256, SMEM1>>>(O,  cw0, T1, HCH, ICH);
            actnorm_kernel<<<BATCH * ICH, 256>>>(T1, nullptr, T1);
            mma_conv<7><<<dim3(S_LEN / 128, ICH / 128, BATCH), 256, SMEM7>>>(T1, cw1, T2, ICH, ICH);
            actnorm_kernel<<<BATCH * ICH, 256>>>(T2, nullptr, T2);
            mma_conv<1><<<dim3(S_LEN / 128, HCH / 128, BATCH), 256, SMEM1>>>(T2, cw2, dst, ICH, HCH);
        }
        gate_kernel<<<(BATCH * S_LEN) / 256, 256>>>(D, P, Sb, pb, O);
        actnorm_kernel<<<BATCH * HCH, 256>>>(O, pa, pa);
        float* t = pa; pa = pb; pb = t;
    }

    concat_kernel<<<(BATCH * 2 * HCH * S_LEN) / 256, 256>>>(pa, pb, T1);
    mma_conv<1><<<dim3(S_LEN / 128, NOUT / 128, BATCH), 256, SMEM1>>>(T1, out_w, D, 2 * HCH, NOUT);
    loss_kernel<<<(BATCH * S_LEN) / 256, 256>>>(D, out_b, tgt, NLL);
    reduce_mean_kernel<<<1, 256>>>(NLL, out);
}